// round 14
// baseline (speedup 1.0000x reference)
#include <cuda_runtime.h>
#include <cuda_bf16.h>
#include <cuda_fp16.h>
#include <cstdint>

#define HEADS 16
#define DHEAD 64
#define NSEQ  2048
#define NB    2
#define INNER 1024
#define NQKV  3072
#define MTOK  4096
#define KDIM  1024

// ---------------- scratch (device globals; no runtime allocation) ----------------
__device__ float g_q[NB * HEADS * NSEQ * DHEAD];
__device__ float g_k[NB * HEADS * NSEQ * DHEAD];
__device__ float g_v[NB * HEADS * NSEQ * DHEAD];

__device__ __nv_bfloat16 g_xhi[MTOK * KDIM];
__device__ __nv_bfloat16 g_xlo[MTOK * KDIM];
__device__ __nv_bfloat16 g_wqkvT_hi[NQKV * KDIM];
__device__ __nv_bfloat16 g_wqkvT_lo[NQKV * KDIM];
__device__ __nv_bfloat16 g_woutT_hi[INNER * KDIM];
__device__ __nv_bfloat16 g_woutT_lo[INNER * KDIM];
__device__ __nv_bfloat16 g_ahi[MTOK * INNER];
__device__ __nv_bfloat16 g_alo[MTOK * INNER];

__device__ __nv_bfloat16 g_qhi[NB * HEADS * NSEQ * DHEAD];
__device__ __nv_bfloat16 g_qlo[NB * HEADS * NSEQ * DHEAD];
__device__ __nv_bfloat16 g_khi[NB * HEADS * NSEQ * DHEAD];
__device__ __nv_bfloat16 g_klo[NB * HEADS * NSEQ * DHEAD];
__device__ __half        g_vT16[NB * HEADS * DHEAD * NSEQ];   // [bh][d][n]

__device__ __forceinline__ void split2(float v, __nv_bfloat16& h, __nv_bfloat16& l) {
    h = __float2bfloat16(v);
    l = __float2bfloat16(v - __bfloat162float(h));
}
__device__ __forceinline__ uint32_t smem_to_u32(const void* p) {
    uint32_t a;
    asm("{ .reg .u64 t; cvta.to.shared.u64 t, %1; cvt.u32.u64 %0, t; }" : "=r"(a) : "l"(p));
    return a;
}

// mma.sync m16n8k16 bf16 -> fp32
__device__ __forceinline__ void mma16816(float* c, const uint32_t* a, const uint32_t* b) {
    asm volatile(
        "mma.sync.aligned.m16n8k16.row.col.f32.bf16.bf16.f32 "
        "{%0,%1,%2,%3}, {%4,%5,%6,%7}, {%8,%9}, {%0,%1,%2,%3};"
        : "+f"(c[0]), "+f"(c[1]), "+f"(c[2]), "+f"(c[3])
        : "r"(a[0]), "r"(a[1]), "r"(a[2]), "r"(a[3]), "r"(b[0]), "r"(b[1]));
}
// mma.sync m16n8k16 fp16 -> fp32
__device__ __forceinline__ void mma16816h(float* c, const uint32_t* a, const uint32_t* b) {
    asm volatile(
        "mma.sync.aligned.m16n8k16.row.col.f32.f16.f16.f32 "
        "{%0,%1,%2,%3}, {%4,%5,%6,%7}, {%8,%9}, {%0,%1,%2,%3};"
        : "+f"(c[0]), "+f"(c[1]), "+f"(c[2]), "+f"(c[3])
        : "r"(a[0]), "r"(a[1]), "r"(a[2]), "r"(a[3]), "r"(b[0]), "r"(b[1]));
}
// ldmatrix x4
__device__ __forceinline__ void ldsm_x4(uint32_t& r0, uint32_t& r1, uint32_t& r2, uint32_t& r3,
                                        uint32_t addr) {
    asm volatile("ldmatrix.sync.aligned.m8n8.x4.shared.b16 {%0,%1,%2,%3}, [%4];"
                 : "=r"(r0), "=r"(r1), "=r"(r2), "=r"(r3) : "r"(addr));
}
// cp.async 16B
__device__ __forceinline__ void cp16(uint32_t dst, const void* src) {
    asm volatile("cp.async.ca.shared.global [%0], [%1], 16;" :: "r"(dst), "l"(src) : "memory");
}
#define CP_COMMIT() asm volatile("cp.async.commit_group;" ::: "memory")
#define CP_WAIT0()  asm volatile("cp.async.wait_group 0;" ::: "memory")
#define CP_WAIT1()  asm volatile("cp.async.wait_group 1;" ::: "memory")

// ============================ conversion kernels ============================
__global__ __launch_bounds__(256) void split_x_kernel(const float* __restrict__ x)
{
    int idx = (blockIdx.x * 256 + threadIdx.x) * 4;
    float4 v = *(const float4*)(x + idx);
    __nv_bfloat16 h0, h1, h2, h3, l0, l1, l2, l3;
    split2(v.x, h0, l0); split2(v.y, h1, l1); split2(v.z, h2, l2); split2(v.w, h3, l3);
    *(__nv_bfloat162*)(g_xhi + idx)     = __nv_bfloat162(h0, h1);
    *(__nv_bfloat162*)(g_xhi + idx + 2) = __nv_bfloat162(h2, h3);
    *(__nv_bfloat162*)(g_xlo + idx)     = __nv_bfloat162(l0, l1);
    *(__nv_bfloat162*)(g_xlo + idx + 2) = __nv_bfloat162(l2, l3);
}

template<int WHICH>
__global__ __launch_bounds__(256) void transpose_split_kernel(const float* __restrict__ W)
{
    const int N = (WHICH == 0) ? NQKV : INNER;
    __nv_bfloat16* WTh = (WHICH == 0) ? g_wqkvT_hi : g_woutT_hi;
    __nv_bfloat16* WTl = (WHICH == 0) ? g_wqkvT_lo : g_woutT_lo;

    __shared__ float tile[32][33];
    int tx = threadIdx.x & 31, ty = threadIdx.x >> 5;
    int bn = blockIdx.x, bk = blockIdx.y;
    #pragma unroll
    for (int i = 0; i < 4; i++)
        tile[ty + 8 * i][tx] = W[(size_t)(bk * 32 + ty + 8 * i) * N + bn * 32 + tx];
    __syncthreads();
    #pragma unroll
    for (int i = 0; i < 4; i++) {
        float v = tile[tx][ty + 8 * i];
        __nv_bfloat16 h, l;
        split2(v, h, l);
        size_t o = (size_t)(bn * 32 + ty + 8 * i) * KDIM + bk * 32 + tx;
        WTh[o] = h; WTl[o] = l;
    }
}

// ============================ HMMA GEMM: K-chunk 64, 3-stage, 2 CTAs/SM ============================
#define GS 72                                   // smem stride in bf16 (36 words = 4 banks mod 32)
#define NCHUNK 48                               // 3 segs * (1024/64)
#define TSTAGE_ELEMS (128 * GS)
#define TSTAGE_BYTES (TSTAGE_ELEMS * 2)         // 18432
#define GEMM_SMEM (6 * TSTAGE_BYTES)            // 3 stages x (A+B) = 110592

__device__ __forceinline__ void gemm_issue(
    int c, int stage, uint32_t As_u, uint32_t Bs_u,
    const __nv_bfloat16* __restrict__ Ahi, const __nv_bfloat16* __restrict__ Alo,
    const __nv_bfloat16* __restrict__ Bhi, const __nv_bfloat16* __restrict__ Blo,
    int by, int bx, int tid)
{
    int seg = c >> 4;
    int kk  = (c & 15) * 64;
    const __nv_bfloat16* Asrc = (seg == 1) ? Alo : Ahi;
    const __nv_bfloat16* Bsrc = (seg == 2) ? Blo : Bhi;
    const uint32_t so = stage * TSTAGE_BYTES;
    const int r0 = tid >> 3;           // 0..31
    const int cc = (tid & 7) * 8;      // 0..56
    #pragma unroll
    for (int i = 0; i < 4; i++) {
        int row = r0 + i * 32;
        cp16(As_u + so + (row * GS + cc) * 2,
             Asrc + (size_t)(by * 128 + row) * KDIM + kk + cc);
        cp16(Bs_u + so + (row * GS + cc) * 2,
             Bsrc + (size_t)(bx * 128 + row) * KDIM + kk + cc);
    }
}

template<int MODE>
__global__ __launch_bounds__(256, 2) void mma_gemm_kernel(const float* __restrict__ bias,
                                                          float* __restrict__ Cout)
{
    const __nv_bfloat16* __restrict__ Ahi = (MODE == 0) ? g_xhi : g_ahi;
    const __nv_bfloat16* __restrict__ Alo = (MODE == 0) ? g_xlo : g_alo;
    const __nv_bfloat16* __restrict__ Bhi = (MODE == 0) ? g_wqkvT_hi : g_woutT_hi;
    const __nv_bfloat16* __restrict__ Blo = (MODE == 0) ? g_wqkvT_lo : g_woutT_lo;

    extern __shared__ __align__(16) __nv_bfloat16 smg[];
    const uint32_t As_u = smem_to_u32(smg);                    // stages 0..2 of A
    const uint32_t Bs_u = As_u + 3 * TSTAGE_BYTES;             // stages 0..2 of B

    const int tid  = threadIdx.x;
    const int lane = tid & 31, wid = tid >> 5;
    const int wm = wid & 1, wn = wid >> 1;
    const int bx = blockIdx.x, by = blockIdx.y;

    uint32_t a_off[4], b_off[2];
    #pragma unroll
    for (int mt = 0; mt < 4; mt++)
        a_off[mt] = ((wm * 64 + mt * 16 + (lane & 15)) * GS + (lane >> 4) * 8) * 2;
    #pragma unroll
    for (int p = 0; p < 2; p++)
        b_off[p] = ((wn * 32 + p * 16 + (lane & 7) + ((lane >> 4) << 3)) * GS
                    + ((lane >> 3) & 1) * 8) * 2;

    float acc[4][4][4];
    #pragma unroll
    for (int mt = 0; mt < 4; mt++)
        #pragma unroll
        for (int nt = 0; nt < 4; nt++)
            #pragma unroll
            for (int r = 0; r < 4; r++) acc[mt][nt][r] = 0.0f;

    gemm_issue(0, 0, As_u, Bs_u, Ahi, Alo, Bhi, Blo, by, bx, tid);
    CP_COMMIT();
    gemm_issue(1, 1, As_u, Bs_u, Ahi, Alo, Bhi, Blo, by, bx, tid);
    CP_COMMIT();

    for (int c = 0; c < NCHUNK; c++) {
        // chunks c and c+1 may be outstanding; need c complete. Tail: wait all.
        if (c + 2 < NCHUNK) CP_WAIT1(); else CP_WAIT0();
        __syncthreads();
        if (c + 2 < NCHUNK) {
            gemm_issue(c + 2, (c + 2) % 3, As_u, Bs_u, Ahi, Alo, Bhi, Blo, by, bx, tid);
            CP_COMMIT();
        }
        const uint32_t so = (c % 3) * TSTAGE_BYTES;
        #pragma unroll
        for (int ks = 0; ks < 4; ks++) {
            const uint32_t kcB = ks * 32;
            uint32_t a[4][4], b[4][2];
            #pragma unroll
            for (int mt = 0; mt < 4; mt++)
                ldsm_x4(a[mt][0], a[mt][1], a[mt][2], a[mt][3], As_u + so + a_off[mt] + kcB);
            ldsm_x4(b[0][0], b[0][1], b[1][0], b[1][1], Bs_u + so + b_off[0] + kcB);
            ldsm_x4(b[2][0], b[2][1], b[3][0], b[3][1], Bs_u + so + b_off[1] + kcB);
            #pragma unroll
            for (int mt = 0; mt < 4; mt++)
                #pragma unroll
                for (int nt = 0; nt < 4; nt++)
                    mma16816(acc[mt][nt], a[mt], b[nt]);
        }
    }

    const int g  = lane >> 2, tg = lane & 3;
    #pragma unroll
    for (int mt = 0; mt < 4; mt++) {
        #pragma unroll
        for (int nt = 0; nt < 4; nt++) {
            int row0 = by * 128 + wm * 64 + mt * 16 + g;
            int col  = bx * 128 + wn * 32 + nt * 8 + tg * 2;
            if (MODE == 0) {
                const int sidx = col >> 10;
                const int h    = (col >> 6) & 15;
                const int d0   = col & 63;
                const float mul = (sidx == 0) ? 0.125f : 1.0f;
                float* dst = (sidx == 0) ? g_q : (sidx == 1) ? g_k : g_v;
                #pragma unroll
                for (int rr = 0; rr < 2; rr++) {
                    int row = row0 + rr * 8;
                    int b_ = row >> 11, nn = row & 2047;
                    float2 val = make_float2(acc[mt][nt][2 * rr] * mul, acc[mt][nt][2 * rr + 1] * mul);
                    *(float2*)(dst + (((b_ * HEADS + h) * NSEQ + nn) * DHEAD + d0)) = val;
                }
            } else {
                float2 bb = *(const float2*)(bias + col);
                #pragma unroll
                for (int rr = 0; rr < 2; rr++) {
                    int row = row0 + rr * 8;
                    float2 val = make_float2(acc[mt][nt][2 * rr] + bb.x, acc[mt][nt][2 * rr + 1] + bb.y);
                    *(float2*)(Cout + (size_t)row * INNER + col) = val;
                }
            }
        }
    }
}

// ============================ RoPE + hi/lo bf16 split for Q,K ============================
__global__ __launch_bounds__(256) void rope_split_kernel()
{
    int idx = blockIdx.x * blockDim.x + threadIdx.x;
    int d  = idx & 31;
    int nn = (idx >> 5) & 2047;
    int bh = idx >> 16;

    float theta = __powf(10000.0f, -(float)d * (1.0f / 32.0f));
    float ang = (float)nn * theta;
    float sv, cv;
    sincosf(ang, &sv, &cv);

    int base = (bh * NSEQ + nn) * DHEAD + d;
    {
        float x1 = g_q[base], x2 = g_q[base + 32];
        float r1 = x1 * cv - x2 * sv;
        float r2 = x1 * sv + x2 * cv;
        __nv_bfloat16 h, l;
        split2(r1, h, l); g_qhi[base] = h;      g_qlo[base] = l;
        split2(r2, h, l); g_qhi[base + 32] = h; g_qlo[base + 32] = l;
    }
    {
        float x1 = g_k[base], x2 = g_k[base + 32];
        float r1 = x1 * cv - x2 * sv;
        float r2 = x1 * sv + x2 * cv;
        __nv_bfloat16 h, l;
        split2(r1, h, l); g_khi[base] = h;      g_klo[base] = l;
        split2(r2, h, l); g_khi[base + 32] = h; g_klo[base + 32] = l;
    }
}

// ============================ V transpose -> fp16 [bh][d][n] ============================
__global__ __launch_bounds__(256) void v_prep_kernel()
{
    __shared__ float tile[32][33];
    int tx = threadIdx.x & 31, ty = threadIdx.x >> 5;
    int n0 = blockIdx.x * 32, d0 = blockIdx.y * 32, bh = blockIdx.z;
    #pragma unroll
    for (int i = 0; i < 4; i++)
        tile[ty + 8 * i][tx] = g_v[((size_t)bh * NSEQ + n0 + ty + 8 * i) * DHEAD + d0 + tx];
    __syncthreads();
    #pragma unroll
    for (int i = 0; i < 4; i++)
        g_vT16[((size_t)bh * DHEAD + d0 + ty + 8 * i) * NSEQ + n0 + tx] =
            __float2half(tile[tx][ty + 8 * i]);
}

// ============================ HMMA flash attention: Ps aliases K, 2 CTAs/SM ============================
#define QS 72
#define PS 136

#define SM_QHI  0
#define SM_QLO  (SM_QHI + 128 * QS * 2)          // 18432
#define SM_KHI  (SM_QLO + 128 * QS * 2)          // 36864
#define SM_KLO  (SM_KHI + 128 * QS * 2)          // 55296
#define SM_PS   SM_KHI                            // alias: Ps (34816 B) over Kh+Kl (36864 B)
#define SM_VT   (SM_KLO + 128 * QS * 2)          // 73728
#define SM_PMAX (SM_VT + 64 * PS * 2)            // 91136
#define SM_PSUM (SM_PMAX + 128 * 4 * 4)
#define SM_MROW (SM_PSUM + 128 * 4 * 4)
#define SM_LROW (SM_MROW + 128 * 4)
#define SM_ALPH (SM_LROW + 128 * 4)
#define SM_ATTN (SM_ALPH + 128 * 4)              // 96768 -> 2 CTAs/SM

__global__ __launch_bounds__(256, 2) void attn_mma_kernel()
{
    extern __shared__ __align__(16) char smc[];
    __nv_bfloat16* Qh = (__nv_bfloat16*)(smc + SM_QHI);
    __nv_bfloat16* Ql = (__nv_bfloat16*)(smc + SM_QLO);
    __nv_bfloat16* Kh = (__nv_bfloat16*)(smc + SM_KHI);
    __nv_bfloat16* Kl = (__nv_bfloat16*)(smc + SM_KLO);
    __half*        Vt = (__half*)(smc + SM_VT);
    __half*        Pp = (__half*)(smc + SM_PS);     // aliases Kh/Kl
    float* pmax  = (float*)(smc + SM_PMAX);
    float* psum  = (float*)(smc + SM_PSUM);
    float* m_row = (float*)(smc + SM_MROW);
    float* l_row = (float*)(smc + SM_LROW);
    float* alph  = (float*)(smc + SM_ALPH);

    const int tid  = threadIdx.x;
    const int lane = tid & 31, wid = tid >> 5;
    const int wm = wid & 1, wn = wid >> 1;
    const int g  = lane >> 2, tg = lane & 3;
    const int qt = blockIdx.x, bh = blockIdx.y;

    const uint32_t Qh_u = smem_to_u32(Qh), Ql_u = smem_to_u32(Ql);
    const uint32_t Kh_u = smem_to_u32(Kh), Kl_u = smem_to_u32(Kl);
    const uint32_t Vt_u = smem_to_u32(Vt), Pp_u = smem_to_u32(Pp);

    uint32_t qa_off[4], kb_off[2], pa_off[4], vb_off;
    #pragma unroll
    for (int mt = 0; mt < 4; mt++) {
        qa_off[mt] = ((wm * 64 + mt * 16 + (lane & 15)) * QS + (lane >> 4) * 8) * 2;
        pa_off[mt] = ((wm * 64 + mt * 16 + (lane & 15)) * PS + (lane >> 4) * 8) * 2;
    }
    #pragma unroll
    for (int p = 0; p < 2; p++)
        kb_off[p] = ((wn * 32 + p * 16 + (lane & 7) + ((lane >> 4) << 3)) * QS
                     + ((lane >> 3) & 1) * 8) * 2;
    vb_off = ((wn * 16 + (lane & 7) + ((lane >> 4) << 3)) * PS + ((lane >> 3) & 1) * 8) * 2;

    const size_t qkbase = (size_t)bh * NSEQ * DHEAD;

    #pragma unroll
    for (int i = 0; i < 4; i++) {
        int f = tid + i * 256;
        int row = f >> 3, c8 = (f & 7) * 8;
        size_t src = qkbase + (size_t)(qt * 128 + row) * DHEAD + c8;
        *(uint4*)&Qh[row * QS + c8] = *(const uint4*)(g_qhi + src);
        *(uint4*)&Ql[row * QS + c8] = *(const uint4*)(g_qlo + src);
    }
    if (tid < 128) { m_row[tid] = -1e30f; l_row[tid] = 0.0f; }

    float o[4][2][4];
    #pragma unroll
    for (int mt = 0; mt < 4; mt++)
        #pragma unroll
        for (int nt = 0; nt < 2; nt++)
            #pragma unroll
            for (int r = 0; r < 4; r++) o[mt][nt][r] = 0.0f;

    for (int kt = 0; kt < NSEQ / 128; kt++) {
        __syncthreads();   // prior PV reads of Pp (=K region) and Vt complete

        #pragma unroll
        for (int i = 0; i < 4; i++) {
            int f = tid + i * 256;
            int row = f >> 3, c8 = (f & 7) * 8;
            size_t src = qkbase + (size_t)(kt * 128 + row) * DHEAD + c8;
            *(uint4*)&Kh[row * QS + c8] = *(const uint4*)(g_khi + src);
            *(uint4*)&Kl[row * QS + c8] = *(const uint4*)(g_klo + src);
        }
        #pragma unroll
        for (int i = 0; i < 4; i++) {
            int f = tid + i * 256;
            int row = f >> 4, c8 = (f & 15) * 8;
            *(uint4*)&Vt[row * PS + c8] =
                *(const uint4*)(g_vT16 + ((size_t)bh * DHEAD + row) * NSEQ + kt * 128 + c8);
        }
        __syncthreads();

        float s[4][4][4];
        #pragma unroll
        for (int mt = 0; mt < 4; mt++)
            #pragma unroll
            for (int nt = 0; nt < 4; nt++)
                #pragma unroll
                for (int r = 0; r < 4; r++) s[mt][nt][r] = 0.0f;

        #pragma unroll
        for (int seg = 0; seg < 3; seg++) {
            const uint32_t Aop_u = (seg == 1) ? Ql_u : Qh_u;
            const uint32_t Bop_u = (seg == 2) ? Kl_u : Kh_u;
            #pragma unroll
            for (int ks = 0; ks < 4; ks++) {
                const uint32_t kcB = ks * 32;
                uint32_t a[4][4], b[4][2];
                #pragma unroll
                for (int mt = 0; mt < 4; mt++)
                    ldsm_x4(a[mt][0], a[mt][1], a[mt][2], a[mt][3], Aop_u + qa_off[mt] + kcB);
                ldsm_x4(b[0][0], b[0][1], b[1][0], b[1][1], Bop_u + kb_off[0] + kcB);
                ldsm_x4(b[2][0], b[2][1], b[3][0], b[3][1], Bop_u + kb_off[1] + kcB);
                #pragma unroll
                for (int mt = 0; mt < 4; mt++)
                    #pragma unroll
                    for (int nt = 0; nt < 4; nt++)
                        mma16816(s[mt][nt], a[mt], b[nt]);
            }
        }

        #pragma unroll
        for (int mt = 0; mt < 4; mt++) {
            float mx0 = -1e30f, mx1 = -1e30f;
            #pragma unroll
            for (int nt = 0; nt < 4; nt++) {
                mx0 = fmaxf(mx0, fmaxf(s[mt][nt][0], s[mt][nt][1]));
                mx1 = fmaxf(mx1, fmaxf(s[mt][nt][2], s[mt][nt][3]));
            }
            mx0 = fmaxf(mx0, __shfl_xor_sync(0xffffffffu, mx0, 1));
            mx0 = fmaxf(mx0, __shfl_xor_sync(0xffffffffu, mx0, 2));
            mx1 = fmaxf(mx1, __shfl_xor_sync(0xffffffffu, mx1, 1));
            mx1 = fmaxf(mx1, __shfl_xor_sync(0xffffffffu, mx1, 2));
            if (tg == 0) {
                int r0 = wm * 64 + mt * 16 + g;
                pmax[r0 * 4 + wn] = mx0;
                pmax[(r0 + 8) * 4 + wn] = mx1;
            }
        }
        __syncthreads();   // all K-fragment reads complete before Pp writes below

        if (tid < 128) {
            float mo = m_row[tid];
            float mn = fmaxf(fmaxf(pmax[tid * 4 + 0], pmax[tid * 4 + 1]),
                             fmaxf(pmax[tid * 4 + 2], pmax[tid * 4 + 3]));
            mn = fmaxf(mo, mn);
            alph[tid] = __expf(mo - mn);
            m_row[tid] = mn;
        }
        __syncthreads();

        #pragma unroll
        for (int mt = 0; mt < 4; mt++) {
            int r0 = wm * 64 + mt * 16 + g;
            float al0 = alph[r0], al1 = alph[r0 + 8];
            #pragma unroll
            for (int nt = 0; nt < 2; nt++) {
                o[mt][nt][0] *= al0; o[mt][nt][1] *= al0;
                o[mt][nt][2] *= al1; o[mt][nt][3] *= al1;
            }
            float m0 = m_row[r0], m1 = m_row[r0 + 8];
            float s0 = 0.0f, s1 = 0.0f;
            #pragma unroll
            for (int nt = 0; nt < 4; nt++) {
                float p0 = __expf(s[mt][nt][0] - m0);
                float p1 = __expf(s[mt][nt][1] - m0);
                float p2 = __expf(s[mt][nt][2] - m1);
                float p3 = __expf(s[mt][nt][3] - m1);
                __half2 h01 = __floats2half2_rn(p0, p1);
                __half2 h23 = __floats2half2_rn(p2, p3);
                int col = wn * 32 + nt * 8 + tg * 2;
                *(__half2*)&Pp[r0 * PS + col]       = h01;
                *(__half2*)&Pp[(r0 + 8) * PS + col] = h23;
                s0 += __low2float(h01) + __high2float(h01);
                s1 += __low2float(h23) + __high2float(h23);
            }
            s0 += __shfl_xor_sync(0xffffffffu, s0, 1);
            s0 += __shfl_xor_sync(0xffffffffu, s0, 2);
            s1 += __shfl_xor_sync(0xffffffffu, s1, 1);
            s1 += __shfl_xor_sync(0xffffffffu, s1, 2);
            if (tg == 0) {
                psum[r0 * 4 + wn] = s0;
                psum[(r0 + 8) * 4 + wn] = s1;
            }
        }
        __syncthreads();

        if (tid < 128) {
            l_row[tid] = l_row[tid] * alph[tid] +
                (psum[tid * 4 + 0] + psum[tid * 4 + 1] + psum[tid * 4 + 2] + psum[tid * 4 + 3]);
        }

        #pragma unroll
        for (int ks = 0; ks < 8; ks++) {
            const uint32_t kcB = ks * 32;
            uint32_t a[4][4], b[2][2];
            #pragma unroll
            for (int mt = 0; mt < 4; mt++)
                ldsm_x4(a[mt][0], a[mt][1], a[mt][2], a[mt][3], Pp_u + pa_off[mt] + kcB);
            ldsm_x4(b[0][0], b[0][1], b[1][0], b[1][1], Vt_u + vb_off + kcB);
            #pragma unroll
            for (int mt = 0; mt < 4; mt++)
                #pragma unroll
                for (int nt = 0; nt < 2; nt++)
                    mma16816h(o[mt][nt], a[mt], b[nt]);
        }
    }

    __syncthreads();

    const int b_ = bh >> 4;
    const int h  = bh & 15;
    #pragma unroll
    for (int mt = 0; mt < 4; mt++) {
        int r0 = wm * 64 + mt * 16 + g;
        float inv0 = 1.0f / l_row[r0];
        float inv1 = 1.0f / l_row[r0 + 8];
        #pragma unroll
        for (int nt = 0; nt < 2; nt++) {
            int d = wn * 16 + nt * 8 + tg * 2;
            #pragma unroll
            for (int rr = 0; rr < 2; rr++) {
                int row = r0 + rr * 8;
                float inv = rr ? inv1 : inv0;
                float v0 = o[mt][nt][2 * rr] * inv;
                float v1 = o[mt][nt][2 * rr + 1] * inv;
                __nv_bfloat16 h0, l0, h1, l1;
                split2(v0, h0, l0); split2(v1, h1, l1);
                size_t base = (size_t)(b_ * NSEQ + qt * 128 + row) * INNER + h * DHEAD + d;
                *(__nv_bfloat162*)(g_ahi + base) = __nv_bfloat162(h0, h1);
                *(__nv_bfloat162*)(g_alo + base) = __nv_bfloat162(l0, l1);
            }
        }
    }
}

// ============================ launch ============================
extern "C" void kernel_launch(void* const* d_in, const int* in_sizes, int n_in,
                              void* d_out, int out_size)
{
    const float* x     = (const float*)d_in[0];
    const float* w_qkv = (const float*)d_in[1];
    const float* w_out = (const float*)d_in[2];
    const float* b_out = (const float*)d_in[3];
    float* out = (float*)d_out;

    cudaFuncSetAttribute(attn_mma_kernel, cudaFuncAttributeMaxDynamicSharedMemorySize, SM_ATTN);
    cudaFuncSetAttribute(mma_gemm_kernel<0>, cudaFuncAttributeMaxDynamicSharedMemorySize, GEMM_SMEM);
    cudaFuncSetAttribute(mma_gemm_kernel<1>, cudaFuncAttributeMaxDynamicSharedMemorySize, GEMM_SMEM);

    split_x_kernel<<<MTOK * KDIM / 4 / 256, 256>>>(x);
    transpose_split_kernel<0><<<dim3(NQKV / 32, KDIM / 32), 256>>>(w_qkv);
    transpose_split_kernel<1><<<dim3(INNER / 32, KDIM / 32), 256>>>(w_out);

    mma_gemm_kernel<0><<<dim3(NQKV / 128, MTOK / 128), 256, GEMM_SMEM>>>(nullptr, nullptr);

    rope_split_kernel<<<(NB * HEADS * NSEQ * 32) / 256, 256>>>();
    v_prep_kernel<<<dim3(NSEQ / 32, DHEAD / 32, NB * HEADS), 256>>>();

    attn_mma_kernel<<<dim3(NSEQ / 128, NB * HEADS), 256, SM_ATTN>>>();

    mma_gemm_kernel<1><<<dim3(INNER / 128, MTOK / 128), 256, GEMM_SMEM>>>(b_out, out);
}

// round 16
// speedup vs baseline: 1.1352x; 1.1352x over previous
#include <cuda_runtime.h>
#include <cuda_bf16.h>
#include <cuda_fp16.h>
#include <cstdint>

#define HEADS 16
#define DHEAD 64
#define NSEQ  2048
#define NB    2
#define INNER 1024
#define NQKV  3072
#define MTOK  4096
#define KDIM  1024

// ---------------- scratch (device globals; no runtime allocation) ----------------
__device__ float g_q[NB * HEADS * NSEQ * DHEAD];
__device__ float g_k[NB * HEADS * NSEQ * DHEAD];
__device__ float g_v[NB * HEADS * NSEQ * DHEAD];

__device__ __nv_bfloat16 g_xhi[MTOK * KDIM];
__device__ __nv_bfloat16 g_xlo[MTOK * KDIM];
__device__ __nv_bfloat16 g_wqkvT_hi[NQKV * KDIM];
__device__ __nv_bfloat16 g_wqkvT_lo[NQKV * KDIM];
__device__ __nv_bfloat16 g_woutT_hi[INNER * KDIM];
__device__ __nv_bfloat16 g_woutT_lo[INNER * KDIM];
__device__ __nv_bfloat16 g_ahi[MTOK * INNER];
__device__ __nv_bfloat16 g_alo[MTOK * INNER];

__device__ __nv_bfloat16 g_qhi[NB * HEADS * NSEQ * DHEAD];
__device__ __nv_bfloat16 g_qlo[NB * HEADS * NSEQ * DHEAD];
__device__ __nv_bfloat16 g_khi[NB * HEADS * NSEQ * DHEAD];
__device__ __nv_bfloat16 g_klo[NB * HEADS * NSEQ * DHEAD];
__device__ __half        g_vT16[NB * HEADS * DHEAD * NSEQ];   // [bh][d][n]

__device__ __forceinline__ void split2(float v, __nv_bfloat16& h, __nv_bfloat16& l) {
    h = __float2bfloat16(v);
    l = __float2bfloat16(v - __bfloat162float(h));
}
__device__ __forceinline__ uint32_t smem_to_u32(const void* p) {
    uint32_t a;
    asm("{ .reg .u64 t; cvta.to.shared.u64 t, %1; cvt.u32.u64 %0, t; }" : "=r"(a) : "l"(p));
    return a;
}

// mma.sync m16n8k16 bf16 -> fp32
__device__ __forceinline__ void mma16816(float* c, const uint32_t* a, const uint32_t* b) {
    asm volatile(
        "mma.sync.aligned.m16n8k16.row.col.f32.bf16.bf16.f32 "
        "{%0,%1,%2,%3}, {%4,%5,%6,%7}, {%8,%9}, {%0,%1,%2,%3};"
        : "+f"(c[0]), "+f"(c[1]), "+f"(c[2]), "+f"(c[3])
        : "r"(a[0]), "r"(a[1]), "r"(a[2]), "r"(a[3]), "r"(b[0]), "r"(b[1]));
}
// mma.sync m16n8k16 fp16 -> fp32
__device__ __forceinline__ void mma16816h(float* c, const uint32_t* a, const uint32_t* b) {
    asm volatile(
        "mma.sync.aligned.m16n8k16.row.col.f32.f16.f16.f32 "
        "{%0,%1,%2,%3}, {%4,%5,%6,%7}, {%8,%9}, {%0,%1,%2,%3};"
        : "+f"(c[0]), "+f"(c[1]), "+f"(c[2]), "+f"(c[3])
        : "r"(a[0]), "r"(a[1]), "r"(a[2]), "r"(a[3]), "r"(b[0]), "r"(b[1]));
}
// ldmatrix x4
__device__ __forceinline__ void ldsm_x4(uint32_t& r0, uint32_t& r1, uint32_t& r2, uint32_t& r3,
                                        uint32_t addr) {
    asm volatile("ldmatrix.sync.aligned.m8n8.x4.shared.b16 {%0,%1,%2,%3}, [%4];"
                 : "=r"(r0), "=r"(r1), "=r"(r2), "=r"(r3) : "r"(addr));
}
// cp.async 16B
__device__ __forceinline__ void cp16(uint32_t dst, const void* src) {
    asm volatile("cp.async.ca.shared.global [%0], [%1], 16;" :: "r"(dst), "l"(src) : "memory");
}
#define CP_COMMIT() asm volatile("cp.async.commit_group;" ::: "memory")
#define CP_WAIT0()  asm volatile("cp.async.wait_group 0;" ::: "memory")

// ============================ conversion kernels ============================
__global__ __launch_bounds__(256) void split_x_kernel(const float* __restrict__ x)
{
    int idx = (blockIdx.x * 256 + threadIdx.x) * 4;
    float4 v = *(const float4*)(x + idx);
    __nv_bfloat16 h0, h1, h2, h3, l0, l1, l2, l3;
    split2(v.x, h0, l0); split2(v.y, h1, l1); split2(v.z, h2, l2); split2(v.w, h3, l3);
    *(__nv_bfloat162*)(g_xhi + idx)     = __nv_bfloat162(h0, h1);
    *(__nv_bfloat162*)(g_xhi + idx + 2) = __nv_bfloat162(h2, h3);
    *(__nv_bfloat162*)(g_xlo + idx)     = __nv_bfloat162(l0, l1);
    *(__nv_bfloat162*)(g_xlo + idx + 2) = __nv_bfloat162(l2, l3);
}

template<int WHICH>
__global__ __launch_bounds__(256) void transpose_split_kernel(const float* __restrict__ W)
{
    const int N = (WHICH == 0) ? NQKV : INNER;
    __nv_bfloat16* WTh = (WHICH == 0) ? g_wqkvT_hi : g_woutT_hi;
    __nv_bfloat16* WTl = (WHICH == 0) ? g_wqkvT_lo : g_woutT_lo;

    __shared__ float tile[32][33];
    int tx = threadIdx.x & 31, ty = threadIdx.x >> 5;
    int bn = blockIdx.x, bk = blockIdx.y;
    #pragma unroll
    for (int i = 0; i < 4; i++)
        tile[ty + 8 * i][tx] = W[(size_t)(bk * 32 + ty + 8 * i) * N + bn * 32 + tx];
    __syncthreads();
    #pragma unroll
    for (int i = 0; i < 4; i++) {
        float v = tile[tx][ty + 8 * i];
        __nv_bfloat16 h, l;
        split2(v, h, l);
        size_t o = (size_t)(bn * 32 + ty + 8 * i) * KDIM + bk * 32 + tx;
        WTh[o] = h; WTl[o] = l;
    }
}

// ============================ HMMA GEMM: K-chunk 64, 2-stage, 2 CTAs/SM (R11) ============================
#define GS 72                                   // smem stride in bf16 (36 words = 4 banks mod 32)
#define NCHUNK 48                               // 3 segs * (1024/64)
#define TSTAGE_ELEMS (128 * GS)
#define TSTAGE_BYTES (TSTAGE_ELEMS * 2)         // 18432
#define GEMM_SMEM (4 * TSTAGE_BYTES)            // 2 stages x (A+B) = 73728

__device__ __forceinline__ void gemm_issue(
    int c, int stage, uint32_t As_u, uint32_t Bs_u,
    const __nv_bfloat16* __restrict__ Ahi, const __nv_bfloat16* __restrict__ Alo,
    const __nv_bfloat16* __restrict__ Bhi, const __nv_bfloat16* __restrict__ Blo,
    int by, int bx, int tid)
{
    int seg = c >> 4;
    int kk  = (c & 15) * 64;
    const __nv_bfloat16* Asrc = (seg == 1) ? Alo : Ahi;
    const __nv_bfloat16* Bsrc = (seg == 2) ? Blo : Bhi;
    const uint32_t so = stage * TSTAGE_BYTES;
    const int r0 = tid >> 3;           // 0..31
    const int cc = (tid & 7) * 8;      // 0..56
    #pragma unroll
    for (int i = 0; i < 4; i++) {
        int row = r0 + i * 32;
        cp16(As_u + so + (row * GS + cc) * 2,
             Asrc + (size_t)(by * 128 + row) * KDIM + kk + cc);
        cp16(Bs_u + so + (row * GS + cc) * 2,
             Bsrc + (size_t)(bx * 128 + row) * KDIM + kk + cc);
    }
}

template<int MODE>
__global__ __launch_bounds__(256, 2) void mma_gemm_kernel(const float* __restrict__ bias,
                                                          float* __restrict__ Cout)
{
    const __nv_bfloat16* __restrict__ Ahi = (MODE == 0) ? g_xhi : g_ahi;
    const __nv_bfloat16* __restrict__ Alo = (MODE == 0) ? g_xlo : g_alo;
    const __nv_bfloat16* __restrict__ Bhi = (MODE == 0) ? g_wqkvT_hi : g_woutT_hi;
    const __nv_bfloat16* __restrict__ Blo = (MODE == 0) ? g_wqkvT_lo : g_woutT_lo;

    extern __shared__ __align__(16) __nv_bfloat16 smg[];
    const uint32_t As_u = smem_to_u32(smg);                    // stages 0,1 of A
    const uint32_t Bs_u = As_u + 2 * TSTAGE_BYTES;             // stages 0,1 of B

    const int tid  = threadIdx.x;
    const int lane = tid & 31, wid = tid >> 5;
    const int wm = wid & 1, wn = wid >> 1;
    const int bx = blockIdx.x, by = blockIdx.y;

    uint32_t a_off[4], b_off[2];
    #pragma unroll
    for (int mt = 0; mt < 4; mt++)
        a_off[mt] = ((wm * 64 + mt * 16 + (lane & 15)) * GS + (lane >> 4) * 8) * 2;
    #pragma unroll
    for (int p = 0; p < 2; p++)
        b_off[p] = ((wn * 32 + p * 16 + (lane & 7) + ((lane >> 4) << 3)) * GS
                    + ((lane >> 3) & 1) * 8) * 2;

    float acc[4][4][4];
    #pragma unroll
    for (int mt = 0; mt < 4; mt++)
        #pragma unroll
        for (int nt = 0; nt < 4; nt++)
            #pragma unroll
            for (int r = 0; r < 4; r++) acc[mt][nt][r] = 0.0f;

    gemm_issue(0, 0, As_u, Bs_u, Ahi, Alo, Bhi, Blo, by, bx, tid);
    CP_COMMIT();

    for (int c = 0; c < NCHUNK; c++) {
        CP_WAIT0();
        __syncthreads();   // chunk c visible; all warps past compute of c-1
        if (c + 1 < NCHUNK) {
            gemm_issue(c + 1, (c + 1) & 1, As_u, Bs_u, Ahi, Alo, Bhi, Blo, by, bx, tid);
            CP_COMMIT();
        }
        const uint32_t so = (c & 1) * TSTAGE_BYTES;
        #pragma unroll
        for (int ks = 0; ks < 4; ks++) {
            const uint32_t kcB = ks * 32;
            uint32_t a[4][4], b[4][2];
            #pragma unroll
            for (int mt = 0; mt < 4; mt++)
                ldsm_x4(a[mt][0], a[mt][1], a[mt][2], a[mt][3], As_u + so + a_off[mt] + kcB);
            ldsm_x4(b[0][0], b[0][1], b[1][0], b[1][1], Bs_u + so + b_off[0] + kcB);
            ldsm_x4(b[2][0], b[2][1], b[3][0], b[3][1], Bs_u + so + b_off[1] + kcB);
            #pragma unroll
            for (int mt = 0; mt < 4; mt++)
                #pragma unroll
                for (int nt = 0; nt < 4; nt++)
                    mma16816(acc[mt][nt], a[mt], b[nt]);
        }
    }

    const int g  = lane >> 2, tg = lane & 3;
    #pragma unroll
    for (int mt = 0; mt < 4; mt++) {
        #pragma unroll
        for (int nt = 0; nt < 4; nt++) {
            int row0 = by * 128 + wm * 64 + mt * 16 + g;
            int col  = bx * 128 + wn * 32 + nt * 8 + tg * 2;
            if (MODE == 0) {
                const int sidx = col >> 10;
                const int h    = (col >> 6) & 15;
                const int d0   = col & 63;
                const float mul = (sidx == 0) ? 0.125f : 1.0f;
                float* dst = (sidx == 0) ? g_q : (sidx == 1) ? g_k : g_v;
                #pragma unroll
                for (int rr = 0; rr < 2; rr++) {
                    int row = row0 + rr * 8;
                    int b_ = row >> 11, nn = row & 2047;
                    float2 val = make_float2(acc[mt][nt][2 * rr] * mul, acc[mt][nt][2 * rr + 1] * mul);
                    *(float2*)(dst + (((b_ * HEADS + h) * NSEQ + nn) * DHEAD + d0)) = val;
                }
            } else {
                float2 bb = *(const float2*)(bias + col);
                #pragma unroll
                for (int rr = 0; rr < 2; rr++) {
                    int row = row0 + rr * 8;
                    float2 val = make_float2(acc[mt][nt][2 * rr] + bb.x, acc[mt][nt][2 * rr + 1] + bb.y);
                    *(float2*)(Cout + (size_t)row * INNER + col) = val;
                }
            }
        }
    }
}

// ============================ RoPE + hi/lo bf16 split for Q,K ============================
__global__ __launch_bounds__(256) void rope_split_kernel()
{
    int idx = blockIdx.x * blockDim.x + threadIdx.x;
    int d  = idx & 31;
    int nn = (idx >> 5) & 2047;
    int bh = idx >> 16;

    float theta = __powf(10000.0f, -(float)d * (1.0f / 32.0f));
    float ang = (float)nn * theta;
    float sv, cv;
    sincosf(ang, &sv, &cv);

    int base = (bh * NSEQ + nn) * DHEAD + d;
    {
        float x1 = g_q[base], x2 = g_q[base + 32];
        float r1 = x1 * cv - x2 * sv;
        float r2 = x1 * sv + x2 * cv;
        __nv_bfloat16 h, l;
        split2(r1, h, l); g_qhi[base] = h;      g_qlo[base] = l;
        split2(r2, h, l); g_qhi[base + 32] = h; g_qlo[base + 32] = l;
    }
    {
        float x1 = g_k[base], x2 = g_k[base + 32];
        float r1 = x1 * cv - x2 * sv;
        float r2 = x1 * sv + x2 * cv;
        __nv_bfloat16 h, l;
        split2(r1, h, l); g_khi[base] = h;      g_klo[base] = l;
        split2(r2, h, l); g_khi[base + 32] = h; g_klo[base + 32] = l;
    }
}

// ============================ V transpose -> fp16 [bh][d][n] ============================
__global__ __launch_bounds__(256) void v_prep_kernel()
{
    __shared__ float tile[32][33];
    int tx = threadIdx.x & 31, ty = threadIdx.x >> 5;
    int n0 = blockIdx.x * 32, d0 = blockIdx.y * 32, bh = blockIdx.z;
    #pragma unroll
    for (int i = 0; i < 4; i++)
        tile[ty + 8 * i][tx] = g_v[((size_t)bh * NSEQ + n0 + ty + 8 * i) * DHEAD + d0 + tx];
    __syncthreads();
    #pragma unroll
    for (int i = 0; i < 4; i++)
        g_vT16[((size_t)bh * DHEAD + d0 + ty + 8 * i) * NSEQ + n0 + tx] =
            __float2half(tile[tx][ty + 8 * i]);
}

// ============================ HMMA flash attention: 64-row q-tile, 2 CTAs/SM ============================
// Warp layout: wm = wid&1 -> 32 q-rows (2 mt tiles); wn = wid>>1 -> 32 key-cols (QK) / 16 d-cols (PV).
// s[2][4][4]=32 regs, o[2][2][4]=16 regs -> fits 128-reg cap without spills.
#define QS 72
#define PS 136

#define SM_QHI  0
#define SM_QLO  (SM_QHI + 64 * QS * 2)           // 9216
#define SM_KHI  (SM_QLO + 64 * QS * 2)           // 18432
#define SM_KLO  (SM_KHI + 128 * QS * 2)          // 36864
#define SM_VT   (SM_KLO + 128 * QS * 2)          // 55296
#define SM_PS   (SM_VT + 64 * PS * 2)            // 72704
#define SM_PMAX (SM_PS + 64 * PS * 2)            // 90112
#define SM_PSUM (SM_PMAX + 64 * 4 * 4)           // 91136
#define SM_MROW (SM_PSUM + 64 * 4 * 4)           // 92160
#define SM_LROW (SM_MROW + 64 * 4)               // 92416
#define SM_ALPH (SM_LROW + 64 * 4)               // 92672
#define SM_ATTN (SM_ALPH + 64 * 4)               // 92928 -> 2 CTAs/SM

__global__ __launch_bounds__(256, 2) void attn_mma_kernel()
{
    extern __shared__ __align__(16) char smc[];
    __nv_bfloat16* Qh = (__nv_bfloat16*)(smc + SM_QHI);
    __nv_bfloat16* Ql = (__nv_bfloat16*)(smc + SM_QLO);
    __nv_bfloat16* Kh = (__nv_bfloat16*)(smc + SM_KHI);
    __nv_bfloat16* Kl = (__nv_bfloat16*)(smc + SM_KLO);
    __half*        Vt = (__half*)(smc + SM_VT);
    __half*        Pp = (__half*)(smc + SM_PS);
    float* pmax  = (float*)(smc + SM_PMAX);
    float* psum  = (float*)(smc + SM_PSUM);
    float* m_row = (float*)(smc + SM_MROW);
    float* l_row = (float*)(smc + SM_LROW);
    float* alph  = (float*)(smc + SM_ALPH);

    const int tid  = threadIdx.x;
    const int lane = tid & 31, wid = tid >> 5;
    const int wm = wid & 1, wn = wid >> 1;
    const int g  = lane >> 2, tg = lane & 3;
    const int qt = blockIdx.x, bh = blockIdx.y;

    const uint32_t Qh_u = smem_to_u32(Qh), Ql_u = smem_to_u32(Ql);
    const uint32_t Kh_u = smem_to_u32(Kh), Kl_u = smem_to_u32(Kl);
    const uint32_t Vt_u = smem_to_u32(Vt), Pp_u = smem_to_u32(Pp);

    uint32_t qa_off[2], kb_off[2], pa_off[2], vb_off;
    #pragma unroll
    for (int mt = 0; mt < 2; mt++) {
        qa_off[mt] = ((wm * 32 + mt * 16 + (lane & 15)) * QS + (lane >> 4) * 8) * 2;
        pa_off[mt] = ((wm * 32 + mt * 16 + (lane & 15)) * PS + (lane >> 4) * 8) * 2;
    }
    #pragma unroll
    for (int p = 0; p < 2; p++)
        kb_off[p] = ((wn * 32 + p * 16 + (lane & 7) + ((lane >> 4) << 3)) * QS
                     + ((lane >> 3) & 1) * 8) * 2;
    vb_off = ((wn * 16 + (lane & 7) + ((lane >> 4) << 3)) * PS + ((lane >> 3) & 1) * 8) * 2;

    const size_t qkbase = (size_t)bh * NSEQ * DHEAD;

    // load Q tile (64 rows) hi/lo
    #pragma unroll
    for (int i = 0; i < 2; i++) {
        int f = tid + i * 256;
        int row = f >> 3, c8 = (f & 7) * 8;
        size_t src = qkbase + (size_t)(qt * 64 + row) * DHEAD + c8;
        *(uint4*)&Qh[row * QS + c8] = *(const uint4*)(g_qhi + src);
        *(uint4*)&Ql[row * QS + c8] = *(const uint4*)(g_qlo + src);
    }
    if (tid < 64) { m_row[tid] = -1e30f; l_row[tid] = 0.0f; }

    float o[2][2][4];
    #pragma unroll
    for (int mt = 0; mt < 2; mt++)
        #pragma unroll
        for (int nt = 0; nt < 2; nt++)
            #pragma unroll
            for (int r = 0; r < 4; r++) o[mt][nt][r] = 0.0f;

    for (int kt = 0; kt < NSEQ / 128; kt++) {
        __syncthreads();   // prior PV reads of Pp/Vt complete; Q load visible (kt=0)

        #pragma unroll
        for (int i = 0; i < 4; i++) {
            int f = tid + i * 256;
            int row = f >> 3, c8 = (f & 7) * 8;
            size_t src = qkbase + (size_t)(kt * 128 + row) * DHEAD + c8;
            *(uint4*)&Kh[row * QS + c8] = *(const uint4*)(g_khi + src);
            *(uint4*)&Kl[row * QS + c8] = *(const uint4*)(g_klo + src);
        }
        #pragma unroll
        for (int i = 0; i < 4; i++) {
            int f = tid + i * 256;
            int row = f >> 4, c8 = (f & 15) * 8;
            *(uint4*)&Vt[row * PS + c8] =
                *(const uint4*)(g_vT16 + ((size_t)bh * DHEAD + row) * NSEQ + kt * 128 + c8);
        }
        __syncthreads();

        // S = Q K^T : 3 segments
        float s[2][4][4];
        #pragma unroll
        for (int mt = 0; mt < 2; mt++)
            #pragma unroll
            for (int nt = 0; nt < 4; nt++)
                #pragma unroll
                for (int r = 0; r < 4; r++) s[mt][nt][r] = 0.0f;

        #pragma unroll
        for (int seg = 0; seg < 3; seg++) {
            const uint32_t Aop_u = (seg == 1) ? Ql_u : Qh_u;
            const uint32_t Bop_u = (seg == 2) ? Kl_u : Kh_u;
            #pragma unroll
            for (int ks = 0; ks < 4; ks++) {
                const uint32_t kcB = ks * 32;
                uint32_t a[2][4], b[4][2];
                #pragma unroll
                for (int mt = 0; mt < 2; mt++)
                    ldsm_x4(a[mt][0], a[mt][1], a[mt][2], a[mt][3], Aop_u + qa_off[mt] + kcB);
                ldsm_x4(b[0][0], b[0][1], b[1][0], b[1][1], Bop_u + kb_off[0] + kcB);
                ldsm_x4(b[2][0], b[2][1], b[3][0], b[3][1], Bop_u + kb_off[1] + kcB);
                #pragma unroll
                for (int mt = 0; mt < 2; mt++)
                    #pragma unroll
                    for (int nt = 0; nt < 4; nt++)
                        mma16816(s[mt][nt], a[mt], b[nt]);
            }
        }

        // row max partials + two-level reduce
        #pragma unroll
        for (int mt = 0; mt < 2; mt++) {
            float mx0 = -1e30f, mx1 = -1e30f;
            #pragma unroll
            for (int nt = 0; nt < 4; nt++) {
                mx0 = fmaxf(mx0, fmaxf(s[mt][nt][0], s[mt][nt][1]));
                mx1 = fmaxf(mx1, fmaxf(s[mt][nt][2], s[mt][nt][3]));
            }
            mx0 = fmaxf(mx0, __shfl_xor_sync(0xffffffffu, mx0, 1));
            mx0 = fmaxf(mx0, __shfl_xor_sync(0xffffffffu, mx0, 2));
            mx1 = fmaxf(mx1, __shfl_xor_sync(0xffffffffu, mx1, 1));
            mx1 = fmaxf(mx1, __shfl_xor_sync(0xffffffffu, mx1, 2));
            if (tg == 0) {
                int r0 = wm * 32 + mt * 16 + g;
                pmax[r0 * 4 + wn] = mx0;
                pmax[(r0 + 8) * 4 + wn] = mx1;
            }
        }
        __syncthreads();

        if (tid < 64) {
            float mo = m_row[tid];
            float mn = fmaxf(fmaxf(pmax[tid * 4 + 0], pmax[tid * 4 + 1]),
                             fmaxf(pmax[tid * 4 + 2], pmax[tid * 4 + 3]));
            mn = fmaxf(mo, mn);
            alph[tid] = __expf(mo - mn);
            m_row[tid] = mn;
        }
        __syncthreads();

        // scale O, P=exp(s-m) -> fp16, row sums of rounded P
        #pragma unroll
        for (int mt = 0; mt < 2; mt++) {
            int r0 = wm * 32 + mt * 16 + g;
            float al0 = alph[r0], al1 = alph[r0 + 8];
            #pragma unroll
            for (int nt = 0; nt < 2; nt++) {
                o[mt][nt][0] *= al0; o[mt][nt][1] *= al0;
                o[mt][nt][2] *= al1; o[mt][nt][3] *= al1;
            }
            float m0 = m_row[r0], m1 = m_row[r0 + 8];
            float s0 = 0.0f, s1 = 0.0f;
            #pragma unroll
            for (int nt = 0; nt < 4; nt++) {
                float p0 = __expf(s[mt][nt][0] - m0);
                float p1 = __expf(s[mt][nt][1] - m0);
                float p2 = __expf(s[mt][nt][2] - m1);
                float p3 = __expf(s[mt][nt][3] - m1);
                __half2 h01 = __floats2half2_rn(p0, p1);
                __half2 h23 = __floats2half2_rn(p2, p3);
                int col = wn * 32 + nt * 8 + tg * 2;
                *(__half2*)&Pp[r0 * PS + col]       = h01;
                *(__half2*)&Pp[(r0 + 8) * PS + col] = h23;
                s0 += __low2float(h01) + __high2float(h01);
                s1 += __low2float(h23) + __high2float(h23);
            }
            s0 += __shfl_xor_sync(0xffffffffu, s0, 1);
            s0 += __shfl_xor_sync(0xffffffffu, s0, 2);
            s1 += __shfl_xor_sync(0xffffffffu, s1, 1);
            s1 += __shfl_xor_sync(0xffffffffu, s1, 2);
            if (tg == 0) {
                psum[r0 * 4 + wn] = s0;
                psum[(r0 + 8) * 4 + wn] = s1;
            }
        }
        __syncthreads();

        if (tid < 64) {
            l_row[tid] = l_row[tid] * alph[tid] +
                (psum[tid * 4 + 0] + psum[tid * 4 + 1] + psum[tid * 4 + 2] + psum[tid * 4 + 3]);
        }

        // O += P @ V  (fp16 MMA)
        #pragma unroll
        for (int ks = 0; ks < 8; ks++) {
            const uint32_t kcB = ks * 32;
            uint32_t a[2][4], b[2][2];
            #pragma unroll
            for (int mt = 0; mt < 2; mt++)
                ldsm_x4(a[mt][0], a[mt][1], a[mt][2], a[mt][3], Pp_u + pa_off[mt] + kcB);
            ldsm_x4(b[0][0], b[0][1], b[1][0], b[1][1], Vt_u + vb_off + kcB);
            #pragma unroll
            for (int mt = 0; mt < 2; mt++)
                #pragma unroll
                for (int nt = 0; nt < 2; nt++)
                    mma16816h(o[mt][nt], a[mt], b[nt]);
        }
    }

    __syncthreads();

    // epilogue: O /= l, split to bf16 hi/lo at [b][n][h*64+d]
    const int b_ = bh >> 4;
    const int h  = bh & 15;
    #pragma unroll
    for (int mt = 0; mt < 2; mt++) {
        int r0 = wm * 32 + mt * 16 + g;
        float inv0 = 1.0f / l_row[r0];
        float inv1 = 1.0f / l_row[r0 + 8];
        #pragma unroll
        for (int nt = 0; nt < 2; nt++) {
            int d = wn * 16 + nt * 8 + tg * 2;
            #pragma unroll
            for (int rr = 0; rr < 2; rr++) {
                int row = r0 + rr * 8;
                float inv = rr ? inv1 : inv0;
                float v0 = o[mt][nt][2 * rr] * inv;
                float v1 = o[mt][nt][2 * rr + 1] * inv;
                __nv_bfloat16 h0, l0, h1, l1;
                split2(v0, h0, l0); split2(v1, h1, l1);
                size_t base = (size_t)(b_ * NSEQ + qt * 64 + row) * INNER + h * DHEAD + d;
                *(__nv_bfloat162*)(g_ahi + base) = __nv_bfloat162(h0, h1);
                *(__nv_bfloat162*)(g_alo + base) = __nv_bfloat162(l0, l1);
            }
        }
    }
}

// ============================ launch ============================
extern "C" void kernel_launch(void* const* d_in, const int* in_sizes, int n_in,
                              void* d_out, int out_size)
{
    const float* x     = (const float*)d_in[0];
    const float* w_qkv = (const float*)d_in[1];
    const float* w_out = (const float*)d_in[2];
    const float* b_out = (const float*)d_in[3];
    float* out = (float*)d_out;

    cudaFuncSetAttribute(attn_mma_kernel, cudaFuncAttributeMaxDynamicSharedMemorySize, SM_ATTN);
    cudaFuncSetAttribute(mma_gemm_kernel<0>, cudaFuncAttributeMaxDynamicSharedMemorySize, GEMM_SMEM);
    cudaFuncSetAttribute(mma_gemm_kernel<1>, cudaFuncAttributeMaxDynamicSharedMemorySize, GEMM_SMEM);

    split_x_kernel<<<MTOK * KDIM / 4 / 256, 256>>>(x);
    transpose_split_kernel<0><<<dim3(NQKV / 32, KDIM / 32), 256>>>(w_qkv);
    transpose_split_kernel<1><<<dim3(INNER / 32, KDIM / 32), 256>>>(w_out);

    mma_gemm_kernel<0><<<dim3(NQKV / 128, MTOK / 128), 256, GEMM_SMEM>>>(nullptr, nullptr);

    rope_split_kernel<<<(NB * HEADS * NSEQ * 32) / 256, 256>>>();
    v_prep_kernel<<<dim3(NSEQ / 32, DHEAD / 32, NB * HEADS), 256>>>();

    attn_mma_kernel<<<dim3(NSEQ / 64, NB * HEADS), 256, SM_ATTN>>>();

    mma_gemm_kernel<1><<<dim3(INNER / 128, MTOK / 128), 256, GEMM_SMEM>>>(b_out, out);
}